// round 16
// baseline (speedup 1.0000x reference)
#include <cuda_runtime.h>
#include <cuda_bf16.h>

#define NCTA 128
#define TPB  512
#define FPITERS 1
#define NIN0 10
#define NIN1 8
#define MAXSWEEP 5

// ---------------- device scratch (no allocation allowed) ----------------
__device__ __align__(16) float g_qf[4096];   // mask; later Z
__device__ __align__(16) float g_StS[4096];  // StS; later G (row-major)
__device__ __align__(16) float g_b[4096];    // rhs; later M
__device__ __align__(16) float g_x[4096];
__device__ __align__(16) float g_y[4096];    // matvec y; later Y
__device__ float g_sv[64];
__device__ float g_fs[64];
__device__ int g_cnt = 0;
__device__ int g_gen = 0;    // 128-CTA barrier (monotone gen; replay-safe)
__device__ int g_cnt8 = 0;
__device__ int g_gen8 = 0;   // 8-CTA barrier for the epilogue

__device__ __forceinline__ void gbar_n(int n, int* cnt, int* gen) {
    __threadfence();
    __syncthreads();
    if (threadIdx.x == 0) {
        int my = *(volatile int*)gen;
        int old = atomicAdd(cnt, 1);
        if (old == n - 1) {
            *cnt = 0;
            __threadfence();
            atomicAdd(gen, 1);
        } else {
            while (*(volatile int*)gen == my) { }
        }
    }
    __syncthreads();
    __threadfence();
}
__device__ __forceinline__ void gbar()  { gbar_n(NCTA, &g_cnt,  &g_gen);  }
__device__ __forceinline__ void gbar8() { gbar_n(8,    &g_cnt8, &g_gen8); }

struct SolveSm {
    float Ms[64*65];
    float xs[4096];
    float zs[2][64];
};
struct FinalSm {
    float Gf[64*68];     // column j at Gf[j*68+r]
    float nrm[64];
    float sarr[64];
    float thr_s;
};
union __align__(16) Smem { SolveSm s; FinalSm f; };

__global__ void __launch_bounds__(TPB, 1)
k_all(const float* __restrict__ inp, const float* __restrict__ L,
      const void* __restrict__ mask, const float* __restrict__ D,
      const float* __restrict__ thP, const float* __restrict__ vp,
      const float* __restrict__ netap, const float* __restrict__ lam1p,
      const float* __restrict__ lam2p, const float* __restrict__ rhop,
      const float* __restrict__ S, float* __restrict__ out) {
    __shared__ Smem sm;
    __shared__ int s_badU8, s_off1;
    int t = threadIdx.x;
    int cta = blockIdx.x;

    // ================= phase 0: prep (CTA0), StS (CTA1-4) =====================
    if (cta == 0) {
        if (t == 0) { s_badU8 = 0; s_off1 = 0; }
        __syncthreads();
        const unsigned char* m8 = (const unsigned char*)mask;
        int b1 = 0, b2 = 0;
        for (int i = t; i < 4096; i += TPB) {
            unsigned v = m8[i];
            if (v > 1u) b1 = 1;
            if (v == 1u && (i & 3) != 0) b2 = 1;
        }
        if (b1) s_badU8 = 1;
        if (b2) s_off1 = 1;
        __syncthreads();
        int mode = s_badU8 ? 1 : (s_off1 ? 0 : 2);   // 0=u8,1=f32,2=i32
        float rho = *rhop;
        for (int i = t; i < 4096; i += TPB) {
            bool on;
            if (mode == 0)      on = ((const unsigned char*)mask)[i] != 0;
            else if (mode == 1) on = ((const float*)mask)[i] != 0.0f;
            else                on = ((const int*)mask)[i] != 0;
            g_qf[i] = on ? 1.0f : 0.0f;
            g_b[i]  = rho * (L[i] - thP[i]) + (on ? inp[i] : 0.0f);
        }
    } else if (cta <= 4) {
        for (int i = t; i < 4096; i += TPB) { int h = i >> 6, a = i & 63; sm.s.Ms[h*65 + a] = S[i]; }
        __syncthreads();
        int base = (cta - 1) * 1024;
        #pragma unroll
        for (int k = 0; k < 2; k++) {
            int idx = base + t + k*TPB;
            int a = idx >> 6, b = idx & 63;
            float acc = 0.0f;
            #pragma unroll 16
            for (int h = 0; h < 64; h++) acc += sm.s.Ms[h*65 + a] * sm.s.Ms[h*65 + b];
            g_StS[idx] = acc;
        }
    }
    gbar();   // 1

    float lam1 = *lam1p, lam2 = *lam2p, rho = *rhop;

    if (cta < 64) {
        for (int i = t; i < 4096; i += TPB) { int a = i >> 6, c = i & 63; sm.s.Ms[a*65 + c] = g_StS[i]; }
        __syncthreads();
    }

    // ---------------- apply: x_h = B_h^{-1} r_h (Jacobi, 64 threads/CTA) -------
    auto apply = [&](int useY, int nin) {
        if (cta < 64 && t < 64) {
            int h = cta, u = t;
            float r = g_b[h*64 + u];
            if (useY) r -= lam1 * g_y[h*64 + u];
            float Muu  = sm.s.Ms[u*65 + u];
            float dinv = 1.0f / (rho + g_qf[h*64 + u] + lam2 * Muu);
            float z = useY ? g_x[h*64 + u] : r * dinv;
            int cur = 0;
            sm.s.zs[0][u] = z;
            asm volatile("bar.sync 1, 64;" ::: "memory");
            for (int it = 0; it < nin; it++) {
                float a0=0.f,a1=0.f,a2=0.f,a3=0.f;
                const float* Mr = &sm.s.Ms[u*65];
                const float* zc = sm.s.zs[cur];
                #pragma unroll 16
                for (int c = 0; c < 64; c += 4) {
                    a0 += Mr[c]   * zc[c];
                    a1 += Mr[c+1] * zc[c+1];
                    a2 += Mr[c+2] * zc[c+2];
                    a3 += Mr[c+3] * zc[c+3];
                }
                float acc = (a0+a1) + (a2+a3);
                z = (r - lam2 * (acc - Muu * z)) * dinv;
                if (it + 1 < nin) {
                    sm.s.zs[cur^1][u] = z;
                    asm volatile("bar.sync 1, 64;" ::: "memory");
                    cur ^= 1;
                }
            }
            g_x[h*64 + u] = z;
        }
    };

    // ---------------- matvec: y = D x (all 128 CTAs, HBM-streaming) -----------
    auto matvec = [&]() {
        const float4* x4 = (const float4*)g_x;
        float4* xs4 = (float4*)sm.s.xs;
        for (int i = t; i < 1024; i += TPB) xs4[i] = x4[i];
        __syncthreads();
        int w = t >> 5, lane = t & 31;
        int row0 = cta * 32 + w * 2;
        #pragma unroll
        for (int rr = 0; rr < 2; rr++) {
            int row = row0 + rr;
            const float4* D4 = (const float4*)(D + (size_t)row * 4096);
            float acc = 0.0f;
            #pragma unroll
            for (int it = 0; it < 32; it++) {
                float4 d  = D4[lane + 32*it];
                float4 xv = xs4[lane + 32*it];
                acc += d.x*xv.x + d.y*xv.y + d.z*xv.z + d.w*xv.w;
            }
            #pragma unroll
            for (int off = 16; off > 0; off >>= 1)
                acc += __shfl_xor_sync(0xffffffffu, acc, off);
            if (lane == 0) g_y[row] = acc;
        }
        __syncthreads();
    };

    apply(0, NIN0);
    gbar();   // 2
    for (int it = 0; it < FPITERS; it++) {
        matvec();
        gbar();
        apply(1, NIN1);
        gbar();
    }

    // CTAs 8..127: remaining work uses 8 CTAs; exit now.
    if (cta >= 8) return;

    // ========== blocked register-resident Jacobi SVD on CTA0 ==================
    if (cta == 0) {
        float* Gf = sm.f.Gf;
        float2* G2 = (float2*)sm.f.Gf;   // col c, row-pair l at G2[c*34 + l]
        float* nrmS = sm.f.nrm;
        int lane = t & 31, w = t >> 5;

        for (int i = t; i < 4096; i += TPB) {
            int r = i >> 6, j = i & 63;
            Gf[j*68 + r] = g_x[i] + thP[i];
        }
        __syncthreads();
        if (t < 64) {
            float acc = 0.0f;
            #pragma unroll 16
            for (int r = 0; r < 64; r++) { float g = Gf[t*68 + r]; acc += g*g; }
            nrmS[t] = acc;
        }
        __syncthreads();

        // pair rotation on registers (2 rows/lane); updates norms in registers
        auto ROT = [&](float &a0, float &a1, float &b0, float &b1,
                       float &na, float &nb, float dp) {
            float dpg = copysignf(fmaxf(fabsf(dp), 1e-30f), dp);
            float zeta = __fdividef(nb - na, 2.0f * dpg);
            float tt = copysignf(__fdividef(1.0f, fabsf(zeta) + __fsqrt_rn(1.0f + zeta*zeta)), zeta);
            float c = __frsqrt_rn(1.0f + tt*tt), s = tt * c;
            float x0=a0, x1=a1, y0=b0, y1=b1;
            a0 = c*x0 - s*y0;  b0 = s*x0 + c*y0;
            a1 = c*x1 - s*y1;  b1 = s*x1 + c*y1;
            na -= tt*dpg;  nb += tt*dpg;
        };

        // intra-block tournament tables (8 cols -> 7 rounds x 4 disjoint pairs)
        const int IPa[7][4] = {{7,1,2,3},{7,2,3,4},{7,3,4,5},{7,4,5,6},
                               {7,5,6,0},{7,6,0,1},{7,0,1,2}};
        const int IPb[7][4] = {{0,6,5,4},{1,0,6,5},{2,1,0,6},{3,2,1,0},
                               {4,3,2,1},{5,4,3,2},{6,5,4,3}};

        for (int sweep = 0; sweep < MAXSWEEP; sweep++) {
            for (int bt = 0; bt < 8; bt++) {
                if (w < 4) {
                    int bp, bq;
                    if (bt == 0) { bp = 2*w; bq = 2*w + 1; }
                    else {
                        int tr = bt - 1;
                        if (w == 0) { bp = 7; bq = tr; }
                        else { bp = (tr + w) % 7; bq = (tr + 7 - w) % 7; }
                    }
                    float A0[8],A1[8],B0[8],B1[8],nP[8],nQ[8];
                    #pragma unroll
                    for (int i = 0; i < 8; i++) {
                        float2 u = G2[(bp*8+i)*34 + lane]; A0[i]=u.x; A1[i]=u.y;
                        float2 v = G2[(bq*8+i)*34 + lane]; B0[i]=v.x; B1[i]=v.y;
                        nP[i] = nrmS[bp*8+i]; nQ[i] = nrmS[bq*8+i];
                    }
                    if (bt == 0) {
                        // intra: orthogonalize within each block (both together)
                        #pragma unroll
                        for (int u = 0; u < 7; u++) {
                            float dpv[8];
                            #pragma unroll
                            for (int m = 0; m < 4; m++) {
                                int a = IPa[u][m], b = IPb[u][m];
                                dpv[m]   = A0[a]*A0[b] + A1[a]*A1[b];
                                dpv[4+m] = B0[a]*B0[b] + B1[a]*B1[b];
                            }
                            #pragma unroll
                            for (int o = 16; o; o >>= 1)
                                #pragma unroll
                                for (int i = 0; i < 8; i++)
                                    dpv[i] += __shfl_xor_sync(0xffffffffu, dpv[i], o);
                            #pragma unroll
                            for (int m = 0; m < 4; m++) {
                                int a = IPa[u][m], b = IPb[u][m];
                                ROT(A0[a],A1[a],A0[b],A1[b],nP[a],nP[b],dpv[m]);
                                ROT(B0[a],B1[a],B0[b],B1[b],nQ[a],nQ[b],dpv[4+m]);
                            }
                        }
                    } else {
                        // cross: 8 shifts; pairs (P_i, Q_i) with Q register-rotated
                        for (int s8 = 0; s8 < 8; s8++) {
                            float dpv[8];
                            #pragma unroll
                            for (int i = 0; i < 8; i++)
                                dpv[i] = A0[i]*B0[i] + A1[i]*B1[i];
                            #pragma unroll
                            for (int o = 16; o; o >>= 1)
                                #pragma unroll
                                for (int i = 0; i < 8; i++)
                                    dpv[i] += __shfl_xor_sync(0xffffffffu, dpv[i], o);
                            #pragma unroll
                            for (int i = 0; i < 8; i++)
                                ROT(A0[i],A1[i],B0[i],B1[i],nP[i],nQ[i],dpv[i]);
                            // rotate Q block down by one (static indices)
                            float q0=B0[0], q1=B1[0], qn=nQ[0];
                            #pragma unroll
                            for (int i = 0; i < 7; i++) {
                                B0[i]=B0[i+1]; B1[i]=B1[i+1]; nQ[i]=nQ[i+1];
                            }
                            B0[7]=q0; B1[7]=q1; nQ[7]=qn;
                        }
                    }
                    #pragma unroll
                    for (int i = 0; i < 8; i++) {
                        float2 u; u.x=A0[i]; u.y=A1[i]; G2[(bp*8+i)*34 + lane] = u;
                        float2 v; v.x=B0[i]; v.y=B1[i]; G2[(bq*8+i)*34 + lane] = v;
                    }
                    #pragma unroll
                    for (int i = 0; i < 8; i++)
                        if (lane == i) { nrmS[bp*8+i] = nP[i]; nrmS[bq*8+i] = nQ[i]; }
                }
                __syncthreads();
            }
        }

        // singular values + threshold + spectral factors
        if (t < 64) {
            float acc = 0.0f;
            #pragma unroll 16
            for (int r = 0; r < 64; r++) { float g = Gf[t*68 + r]; acc += g*g; }
            sm.f.sarr[t] = sqrtf(acc);
        }
        __syncthreads();
        if (t == 0) {
            float m = 0.0f;
            for (int j = 0; j < 64; j++) m = fmaxf(m, sm.f.sarr[j]);
            float vv = *vp;
            float tau = 0.4f / (1.0f + expf(-vv));
            sm.f.thr_s = tau * m;
        }
        __syncthreads();
        if (t < 64) {
            float s = sm.f.sarr[t];
            float st = s - sm.f.thr_s;
            g_sv[t] = s;
            g_fs[t] = (st > 0.0f) ? st / (s*s*s) : 0.0f;
        }
        // dump G row-major into dead g_StS
        for (int i = t; i < 4096; i += TPB) {
            int r = i >> 6, j = i & 63;
            g_StS[i] = Gf[j*68 + r];
        }
    }
    gbar8();   // Jacobi results visible to CTAs 0-7

    // ======= parallel DK epilogue: Ltmp = G M G^T X, M = DK(w, N) =============
    float neta = *netap;
    int idx = cta * TPB + t;

    // Phase A: Y[i][c] = sum_r G[r][i] X[r][c]; N -> M
    {
        int i = idx >> 6, c = idx & 63;
        float accY = 0.0f, accN = 0.0f;
        #pragma unroll 8
        for (int r = 0; r < 64; r++) {
            float gri = g_StS[r*64 + i];
            accY += gri * (g_x[r*64 + c] + thP[r*64 + c]);
            accN += gri * g_StS[r*64 + c];
        }
        g_y[idx] = accY;
        float Mv;
        if (i == c) Mv = g_fs[i];
        else {
            float si = g_sv[i], sj = g_sv[c];
            float ni = si*si, nj = sj*sj, dn = nj - ni;
            Mv = (fabsf(dn) > 1e-6f*(ni + nj) + 1e-30f)
                 ? accN * (g_fs[c] - g_fs[i]) / dn : 0.0f;
        }
        g_b[idx] = Mv;
    }
    gbar8();

    // Phase B: Z[i][c] = sum_m M[i][m] Y[m][c]
    {
        int i = idx >> 6, c = idx & 63;
        float acc = 0.0f;
        #pragma unroll 8
        for (int m = 0; m < 64; m++) acc += g_b[i*64 + m] * g_y[m*64 + c];
        g_qf[idx] = acc;
    }
    gbar8();

    // Phase C: Ltmp = G Z ; Ptmp = thP + neta*(x - Ltmp)
    {
        int r = idx >> 6, c = idx & 63;
        float acc = 0.0f;
        #pragma unroll 8
        for (int j = 0; j < 64; j++) acc += g_StS[r*64 + j] * g_qf[j*64 + c];
        out[idx]        = acc;
        out[4096 + idx] = thP[idx] + neta * (g_x[idx] - acc);
    }
}

// ---------------- launch ----------------
extern "C" void kernel_launch(void* const* d_in, const int* in_sizes, int n_in,
                              void* d_out, int out_size) {
    const float* inp  = (const float*)d_in[0];
    const float* L    = (const float*)d_in[1];
    const void*  mask = d_in[2];
    const float* D    = (const float*)d_in[3];
    const float* thP  = (const float*)d_in[4];
    const float* v    = (const float*)d_in[5];
    const float* neta = (const float*)d_in[6];
    const float* lam1 = (const float*)d_in[7];
    const float* lam2 = (const float*)d_in[8];
    const float* rho  = (const float*)d_in[9];
    const float* S    = (const float*)d_in[10];
    float* out = (float*)d_out;

    k_all<<<NCTA, TPB>>>(inp, L, mask, D, thP, v, neta, lam1, lam2, rho, S, out);
}

// round 17
// speedup vs baseline: 1.5702x; 1.5702x over previous
#include <cuda_runtime.h>
#include <cuda_bf16.h>

#define NCTA 128
#define TPB  512
#define FPITERS 1
#define NIN0 10
#define NIN1 8
#define MAXSWEEP 5

// ---------------- device scratch (no allocation allowed) ----------------
__device__ __align__(16) float g_qf[4096];   // mask; later Z
__device__ __align__(16) float g_StS[4096];  // StS; later G (row-major)
__device__ __align__(16) float g_b[4096];    // rhs; later M
__device__ __align__(16) float g_x[4096];
__device__ __align__(16) float g_y[4096];    // matvec y; later Y
__device__ float g_sv[64];
__device__ float g_fs[64];
__device__ int g_cnt = 0;
__device__ int g_gen = 0;    // 128-CTA barrier (monotone gen; replay-safe)
__device__ int g_cnt8 = 0;
__device__ int g_gen8 = 0;   // 8-CTA barrier for the epilogue

__device__ __forceinline__ void gbar_n(int n, int* cnt, int* gen) {
    __threadfence();
    __syncthreads();
    if (threadIdx.x == 0) {
        int my = *(volatile int*)gen;
        int old = atomicAdd(cnt, 1);
        if (old == n - 1) {
            *cnt = 0;
            __threadfence();
            atomicAdd(gen, 1);
        } else {
            while (*(volatile int*)gen == my) { }
        }
    }
    __syncthreads();
    __threadfence();
}
__device__ __forceinline__ void gbar()  { gbar_n(NCTA, &g_cnt,  &g_gen);  }
__device__ __forceinline__ void gbar8() { gbar_n(8,    &g_cnt8, &g_gen8); }

struct SolveSm {
    float Ms[64*65];
    float xs[4096];
    float zs[2][64];
};
struct FinalSm {
    float Gf[64*68];     // column j at Gf[j*68+r]; float2 view stride 34
    float nrm[64];
    float sarr[64];
    float thr_s;
};
union __align__(16) Smem { SolveSm s; FinalSm f; };

__global__ void __launch_bounds__(TPB, 1)
k_all(const float* __restrict__ inp, const float* __restrict__ L,
      const void* __restrict__ mask, const float* __restrict__ D,
      const float* __restrict__ thP, const float* __restrict__ vp,
      const float* __restrict__ netap, const float* __restrict__ lam1p,
      const float* __restrict__ lam2p, const float* __restrict__ rhop,
      const float* __restrict__ S, float* __restrict__ out) {
    __shared__ Smem sm;
    __shared__ int s_badU8, s_off1;
    int t = threadIdx.x;
    int cta = blockIdx.x;

    // ================= phase 0: prep (CTA0), StS (CTA1-4) =====================
    if (cta == 0) {
        if (t == 0) { s_badU8 = 0; s_off1 = 0; }
        __syncthreads();
        const unsigned char* m8 = (const unsigned char*)mask;
        int b1 = 0, b2 = 0;
        for (int i = t; i < 4096; i += TPB) {
            unsigned v = m8[i];
            if (v > 1u) b1 = 1;
            if (v == 1u && (i & 3) != 0) b2 = 1;
        }
        if (b1) s_badU8 = 1;
        if (b2) s_off1 = 1;
        __syncthreads();
        int mode = s_badU8 ? 1 : (s_off1 ? 0 : 2);   // 0=u8,1=f32,2=i32
        float rho = *rhop;
        for (int i = t; i < 4096; i += TPB) {
            bool on;
            if (mode == 0)      on = ((const unsigned char*)mask)[i] != 0;
            else if (mode == 1) on = ((const float*)mask)[i] != 0.0f;
            else                on = ((const int*)mask)[i] != 0;
            g_qf[i] = on ? 1.0f : 0.0f;
            g_b[i]  = rho * (L[i] - thP[i]) + (on ? inp[i] : 0.0f);
        }
    } else if (cta <= 4) {
        for (int i = t; i < 4096; i += TPB) { int h = i >> 6, a = i & 63; sm.s.Ms[h*65 + a] = S[i]; }
        __syncthreads();
        int base = (cta - 1) * 1024;
        #pragma unroll
        for (int k = 0; k < 2; k++) {
            int idx = base + t + k*TPB;
            int a = idx >> 6, b = idx & 63;
            float acc = 0.0f;
            #pragma unroll 16
            for (int h = 0; h < 64; h++) acc += sm.s.Ms[h*65 + a] * sm.s.Ms[h*65 + b];
            g_StS[idx] = acc;
        }
    }
    gbar();   // 1

    float lam1 = *lam1p, lam2 = *lam2p, rho = *rhop;

    if (cta < 64) {
        for (int i = t; i < 4096; i += TPB) { int a = i >> 6, c = i & 63; sm.s.Ms[a*65 + c] = g_StS[i]; }
        __syncthreads();
    }

    // ---------------- apply: x_h = B_h^{-1} r_h (Jacobi, 64 threads/CTA) -------
    auto apply = [&](int useY, int nin) {
        if (cta < 64 && t < 64) {
            int h = cta, u = t;
            float r = g_b[h*64 + u];
            if (useY) r -= lam1 * g_y[h*64 + u];
            float Muu  = sm.s.Ms[u*65 + u];
            float dinv = 1.0f / (rho + g_qf[h*64 + u] + lam2 * Muu);
            float z = useY ? g_x[h*64 + u] : r * dinv;
            int cur = 0;
            sm.s.zs[0][u] = z;
            asm volatile("bar.sync 1, 64;" ::: "memory");
            for (int it = 0; it < nin; it++) {
                float a0=0.f,a1=0.f,a2=0.f,a3=0.f;
                const float* Mr = &sm.s.Ms[u*65];
                const float* zc = sm.s.zs[cur];
                #pragma unroll 16
                for (int c = 0; c < 64; c += 4) {
                    a0 += Mr[c]   * zc[c];
                    a1 += Mr[c+1] * zc[c+1];
                    a2 += Mr[c+2] * zc[c+2];
                    a3 += Mr[c+3] * zc[c+3];
                }
                float acc = (a0+a1) + (a2+a3);
                z = (r - lam2 * (acc - Muu * z)) * dinv;
                if (it + 1 < nin) {
                    sm.s.zs[cur^1][u] = z;
                    asm volatile("bar.sync 1, 64;" ::: "memory");
                    cur ^= 1;
                }
            }
            g_x[h*64 + u] = z;
        }
    };

    // ---------------- matvec: y = D x (all 128 CTAs, HBM-streaming) -----------
    auto matvec = [&]() {
        const float4* x4 = (const float4*)g_x;
        float4* xs4 = (float4*)sm.s.xs;
        for (int i = t; i < 1024; i += TPB) xs4[i] = x4[i];
        __syncthreads();
        int w = t >> 5, lane = t & 31;
        int row0 = cta * 32 + w * 2;
        #pragma unroll
        for (int rr = 0; rr < 2; rr++) {
            int row = row0 + rr;
            const float4* D4 = (const float4*)(D + (size_t)row * 4096);
            float acc = 0.0f;
            #pragma unroll
            for (int it = 0; it < 32; it++) {
                float4 d  = D4[lane + 32*it];
                float4 xv = xs4[lane + 32*it];
                acc += d.x*xv.x + d.y*xv.y + d.z*xv.z + d.w*xv.w;
            }
            #pragma unroll
            for (int off = 16; off > 0; off >>= 1)
                acc += __shfl_xor_sync(0xffffffffu, acc, off);
            if (lane == 0) g_y[row] = acc;
        }
        __syncthreads();
    };

    apply(0, NIN0);
    gbar();   // 2
    for (int it = 0; it < FPITERS; it++) {
        matvec();
        gbar();
        apply(1, NIN1);
        gbar();
    }

    // CTAs 8..127: remaining work uses 8 CTAs; exit now.
    if (cta >= 8) return;

    // ========== blocked register Jacobi SVD on CTA0 (block=4, 8 warps) ========
    if (cta == 0) {
        float* Gf = sm.f.Gf;
        float2* G2 = (float2*)sm.f.Gf;   // col c, row-pair l at G2[c*34 + l]
        float* nrmS = sm.f.nrm;
        int lane = t & 31, w = t >> 5;

        for (int i = t; i < 4096; i += TPB) {
            int r = i >> 6, j = i & 63;
            Gf[j*68 + r] = g_x[i] + thP[i];
        }
        __syncthreads();
        if (t < 64) {
            float acc = 0.0f;
            #pragma unroll 16
            for (int r = 0; r < 64; r++) { float g = Gf[t*68 + r]; acc += g*g; }
            nrmS[t] = acc;
        }
        __syncthreads();

        auto ROT = [&](float &a0, float &a1, float &b0, float &b1,
                       float &na, float &nb, float dp) {
            float dpg = copysignf(fmaxf(fabsf(dp), 1e-30f), dp);
            float zeta = __fdividef(nb - na, 2.0f * dpg);
            float tt = copysignf(__fdividef(1.0f, fabsf(zeta) + __fsqrt_rn(1.0f + zeta*zeta)), zeta);
            float c = __frsqrt_rn(1.0f + tt*tt), s = tt * c;
            float x0=a0, x1=a1, y0=b0, y1=b1;
            a0 = c*x0 - s*y0;  b0 = s*x0 + c*y0;
            a1 = c*x1 - s*y1;  b1 = s*x1 + c*y1;
            na -= tt*dpg;  nb += tt*dpg;
        };
        auto RED4 = [&](float &d0, float &d1, float &d2, float &d3) {
            #pragma unroll
            for (int o = 16; o; o >>= 1) {
                d0 += __shfl_xor_sync(0xffffffffu, d0, o);
                d1 += __shfl_xor_sync(0xffffffffu, d1, o);
                d2 += __shfl_xor_sync(0xffffffffu, d2, o);
                d3 += __shfl_xor_sync(0xffffffffu, d3, o);
            }
        };

        for (int sweep = 0; sweep < MAXSWEEP; sweep++) {
            for (int bt = 0; bt < 16; bt++) {
                if (w < 8) {
                    int bp, bq;
                    if (bt == 0) { bp = w; bq = w + 8; }
                    else {
                        int tr = bt - 1;
                        bp = (w == 0) ? 15 : (tr + w) % 15;
                        bq = (w == 0) ? tr : (tr + 15 - w) % 15;
                    }
                    float A0[4],A1[4],B0[4],B1[4],nA[4],nB[4];
                    #pragma unroll
                    for (int i = 0; i < 4; i++) {
                        float2 u = G2[(bp*4+i)*34 + lane]; A0[i]=u.x; A1[i]=u.y;
                        float2 v = G2[(bq*4+i)*34 + lane]; B0[i]=v.x; B1[i]=v.y;
                        nA[i] = nrmS[bp*4+i]; nB[i] = nrmS[bq*4+i];
                    }
                    if (bt == 0) {
                        // intra-block: 3 sub-rounds of static disjoint pairs
                        {   // (0,1),(2,3) in both blocks
                            float d0 = A0[0]*A0[1]+A1[0]*A1[1];
                            float d1 = A0[2]*A0[3]+A1[2]*A1[3];
                            float d2 = B0[0]*B0[1]+B1[0]*B1[1];
                            float d3 = B0[2]*B0[3]+B1[2]*B1[3];
                            RED4(d0,d1,d2,d3);
                            ROT(A0[0],A1[0],A0[1],A1[1],nA[0],nA[1],d0);
                            ROT(A0[2],A1[2],A0[3],A1[3],nA[2],nA[3],d1);
                            ROT(B0[0],B1[0],B0[1],B1[1],nB[0],nB[1],d2);
                            ROT(B0[2],B1[2],B0[3],B1[3],nB[2],nB[3],d3);
                        }
                        {   // (0,2),(1,3)
                            float d0 = A0[0]*A0[2]+A1[0]*A1[2];
                            float d1 = A0[1]*A0[3]+A1[1]*A1[3];
                            float d2 = B0[0]*B0[2]+B1[0]*B1[2];
                            float d3 = B0[1]*B0[3]+B1[1]*B1[3];
                            RED4(d0,d1,d2,d3);
                            ROT(A0[0],A1[0],A0[2],A1[2],nA[0],nA[2],d0);
                            ROT(A0[1],A1[1],A0[3],A1[3],nA[1],nA[3],d1);
                            ROT(B0[0],B1[0],B0[2],B1[2],nB[0],nB[2],d2);
                            ROT(B0[1],B1[1],B0[3],B1[3],nB[1],nB[3],d3);
                        }
                        {   // (0,3),(1,2)
                            float d0 = A0[0]*A0[3]+A1[0]*A1[3];
                            float d1 = A0[1]*A0[2]+A1[1]*A1[2];
                            float d2 = B0[0]*B0[3]+B1[0]*B1[3];
                            float d3 = B0[1]*B0[2]+B1[1]*B1[2];
                            RED4(d0,d1,d2,d3);
                            ROT(A0[0],A1[0],A0[3],A1[3],nA[0],nA[3],d0);
                            ROT(A0[1],A1[1],A0[2],A1[2],nA[1],nA[2],d1);
                            ROT(B0[0],B1[0],B0[3],B1[3],nB[0],nB[3],d2);
                            ROT(B0[1],B1[1],B0[2],B1[2],nB[1],nB[2],d3);
                        }
                    } else {
                        // cross: 4 shifts; pairs (A_i, B_i) with B register-rotated
                        #pragma unroll
                        for (int s4 = 0; s4 < 4; s4++) {
                            float d0 = A0[0]*B0[0]+A1[0]*B1[0];
                            float d1 = A0[1]*B0[1]+A1[1]*B1[1];
                            float d2 = A0[2]*B0[2]+A1[2]*B1[2];
                            float d3 = A0[3]*B0[3]+A1[3]*B1[3];
                            RED4(d0,d1,d2,d3);
                            ROT(A0[0],A1[0],B0[0],B1[0],nA[0],nB[0],d0);
                            ROT(A0[1],A1[1],B0[1],B1[1],nA[1],nB[1],d1);
                            ROT(A0[2],A1[2],B0[2],B1[2],nA[2],nB[2],d2);
                            ROT(A0[3],A1[3],B0[3],B1[3],nA[3],nB[3],d3);
                            float b0=B0[0], b1=B1[0], bn=nB[0];
                            B0[0]=B0[1]; B1[0]=B1[1]; nB[0]=nB[1];
                            B0[1]=B0[2]; B1[1]=B1[2]; nB[1]=nB[2];
                            B0[2]=B0[3]; B1[2]=B1[3]; nB[2]=nB[3];
                            B0[3]=b0;    B1[3]=b1;    nB[3]=bn;
                        }
                    }
                    #pragma unroll
                    for (int i = 0; i < 4; i++) {
                        float2 u; u.x=A0[i]; u.y=A1[i]; G2[(bp*4+i)*34 + lane] = u;
                        float2 v; v.x=B0[i]; v.y=B1[i]; G2[(bq*4+i)*34 + lane] = v;
                    }
                    if (lane == 0) {
                        #pragma unroll
                        for (int i = 0; i < 4; i++) {
                            nrmS[bp*4+i] = nA[i];
                            nrmS[bq*4+i] = nB[i];
                        }
                    }
                }
                __syncthreads();
            }
        }

        // singular values + threshold + spectral factors
        if (t < 64) {
            float acc = 0.0f;
            #pragma unroll 16
            for (int r = 0; r < 64; r++) { float g = Gf[t*68 + r]; acc += g*g; }
            sm.f.sarr[t] = sqrtf(acc);
        }
        __syncthreads();
        if (t == 0) {
            float m = 0.0f;
            for (int j = 0; j < 64; j++) m = fmaxf(m, sm.f.sarr[j]);
            float vv = *vp;
            float tau = 0.4f / (1.0f + expf(-vv));
            sm.f.thr_s = tau * m;
        }
        __syncthreads();
        if (t < 64) {
            float s = sm.f.sarr[t];
            float st = s - sm.f.thr_s;
            g_sv[t] = s;
            g_fs[t] = (st > 0.0f) ? st / (s*s*s) : 0.0f;
        }
        // dump G row-major into dead g_StS
        for (int i = t; i < 4096; i += TPB) {
            int r = i >> 6, j = i & 63;
            g_StS[i] = Gf[j*68 + r];
        }
    }
    gbar8();   // Jacobi results visible to CTAs 0-7

    // ======= parallel DK epilogue: Ltmp = G M G^T X, M = DK(w, N) =============
    float neta = *netap;
    int idx = cta * TPB + t;

    // Phase A: Y[i][c] = sum_r G[r][i] X[r][c]; N -> M
    {
        int i = idx >> 6, c = idx & 63;
        float accY = 0.0f, accN = 0.0f;
        #pragma unroll 8
        for (int r = 0; r < 64; r++) {
            float gri = g_StS[r*64 + i];
            accY += gri * (g_x[r*64 + c] + thP[r*64 + c]);
            accN += gri * g_StS[r*64 + c];
        }
        g_y[idx] = accY;
        float Mv;
        if (i == c) Mv = g_fs[i];
        else {
            float si = g_sv[i], sj = g_sv[c];
            float ni = si*si, nj = sj*sj, dn = nj - ni;
            Mv = (fabsf(dn) > 1e-6f*(ni + nj) + 1e-30f)
                 ? accN * (g_fs[c] - g_fs[i]) / dn : 0.0f;
        }
        g_b[idx] = Mv;
    }
    gbar8();

    // Phase B: Z[i][c] = sum_m M[i][m] Y[m][c]
    {
        int i = idx >> 6, c = idx & 63;
        float acc = 0.0f;
        #pragma unroll 8
        for (int m = 0; m < 64; m++) acc += g_b[i*64 + m] * g_y[m*64 + c];
        g_qf[idx] = acc;
    }
    gbar8();

    // Phase C: Ltmp = G Z ; Ptmp = thP + neta*(x - Ltmp)
    {
        int r = idx >> 6, c = idx & 63;
        float acc = 0.0f;
        #pragma unroll 8
        for (int j = 0; j < 64; j++) acc += g_StS[r*64 + j] * g_qf[j*64 + c];
        out[idx]        = acc;
        out[4096 + idx] = thP[idx] + neta * (g_x[idx] - acc);
    }
}

// ---------------- launch ----------------
extern "C" void kernel_launch(void* const* d_in, const int* in_sizes, int n_in,
                              void* d_out, int out_size) {
    const float* inp  = (const float*)d_in[0];
    const float* L    = (const float*)d_in[1];
    const void*  mask = d_in[2];
    const float* D    = (const float*)d_in[3];
    const float* thP  = (const float*)d_in[4];
    const float* v    = (const float*)d_in[5];
    const float* neta = (const float*)d_in[6];
    const float* lam1 = (const float*)d_in[7];
    const float* lam2 = (const float*)d_in[8];
    const float* rho  = (const float*)d_in[9];
    const float* S    = (const float*)d_in[10];
    float* out = (float*)d_out;

    k_all<<<NCTA, TPB>>>(inp, L, mask, D, thP, v, neta, lam1, lam2, rho, S, out);
}